// round 13
// baseline (speedup 1.0000x reference)
#include <cuda_runtime.h>
#include <cuda_bf16.h>
#include <mma.h>
#include <cstdint>

using namespace nvcuda;

#define T_STEPS 2048
#define BATCH   256
#define HID     64
#define NG      256
#define NOUT    11
#define LDK     200
#define LDB     208

typedef unsigned long long u64;

__device__ float g_hbuf[(size_t)BATCH * T_STEPS * HID];   // 128 MB
__device__ float g_xp[(size_t)BATCH * T_STEPS * NG];      // 512 MB
__device__ float g_hfin[BATCH * HID];
__device__ __align__(256) __nv_bfloat16 g_wsp[NG * LDB];  // split W_ih

// ---------------- scalar helpers ----------------
__device__ __forceinline__ u64 pack2(float a, float b) {
    u64 r; asm("mov.b64 %0, {%1,%2};" : "=l"(r) : "f"(a), "f"(b)); return r;
}
__device__ __forceinline__ void unpack2(u64 v, float& a, float& b) {
    asm("mov.b64 {%0,%1}, %2;" : "=f"(a), "=f"(b) : "l"(v));
}
__device__ __forceinline__ void ffma2(u64& d, u64 a, u64 b) {
    asm("fma.rn.f32x2 %0, %1, %2, %0;" : "+l"(d) : "l"(a), "l"(b));
}
__device__ __forceinline__ float tanha(float x) {
    float y; asm("tanh.approx.f32 %0, %1;" : "=f"(y) : "f"(x)); return y;
}
__device__ __forceinline__ float sigt(float x) {
    return fmaf(0.5f, tanha(0.5f * x), 0.5f);
}
__device__ __forceinline__ void gbar(int id) {
    asm volatile("bar.sync %0, 128;" :: "r"(id) : "memory");
}
__device__ __forceinline__ void bsplit(float x, uint32_t& hibits, float& lo) {
    uint32_t u = __float_as_uint(x) & 0xFFFF0000u;
    hibits = u;
    lo = x - __uint_as_float(u);
}
__device__ __forceinline__ uint32_t bfpack_rn(float x0, float x1) {
    __nv_bfloat162 h = __floats2bfloat162_rn(x0, x1);
    return *(uint32_t*)&h;
}

// ---------------------------------------------------------------------------
// One-time W_ih split (R12, measured).
// ---------------------------------------------------------------------------
__global__ void wsplit(const float* __restrict__ W_ih)
{
    const int n = threadIdx.x;
    const float4* src = (const float4*)(W_ih + n * HID);
    __nv_bfloat16* br = g_wsp + n * LDB;
#pragma unroll
    for (int i = 0; i < 8; i++) {
        float4 v = src[i * 2];
        float4 w = src[i * 2 + 1];
        uint32_t h0, h1, h2, h3, h4, h5, h6, h7;
        float l0, l1, l2, l3, l4, l5, l6, l7;
        bsplit(v.x, h0, l0); bsplit(v.y, h1, l1);
        bsplit(v.z, h2, l2); bsplit(v.w, h3, l3);
        bsplit(w.x, h4, l4); bsplit(w.y, h5, l5);
        bsplit(w.z, h6, l6); bsplit(w.w, h7, l7);
        uint32_t hp0 = (h0 >> 16) | (h1 & 0xFFFF0000u);
        uint32_t hp1 = (h2 >> 16) | (h3 & 0xFFFF0000u);
        uint32_t hp2 = (h4 >> 16) | (h5 & 0xFFFF0000u);
        uint32_t hp3 = (h6 >> 16) | (h7 & 0xFFFF0000u);
        *(uint32_t*)(br + 8 * i)           = hp0;
        *(uint32_t*)(br + 8 * i + 2)       = hp1;
        *(uint32_t*)(br + 8 * i + 4)       = hp2;
        *(uint32_t*)(br + 8 * i + 6)       = hp3;
        *(uint32_t*)(br + 64 + 8 * i)      = hp0;
        *(uint32_t*)(br + 64 + 8 * i + 2)  = hp1;
        *(uint32_t*)(br + 64 + 8 * i + 4)  = hp2;
        *(uint32_t*)(br + 64 + 8 * i + 6)  = hp3;
        *(uint32_t*)(br + 128 + 8 * i)     = bfpack_rn(l0, l1);
        *(uint32_t*)(br + 128 + 8 * i + 2) = bfpack_rn(l2, l3);
        *(uint32_t*)(br + 128 + 8 * i + 4) = bfpack_rn(l4, l5);
        *(uint32_t*)(br + 128 + 8 * i + 6) = bfpack_rn(l6, l7);
    }
}

// ---------------------------------------------------------------------------
// WMMA x-projection (R12, measured ~330us/layer). Unchanged.
// ---------------------------------------------------------------------------
__global__ __launch_bounds__(128, 4)
void xproj_wmma(int dummy)
{
    __shared__ __align__(16) __nv_bfloat16 As[64 * LDK];

    const int tid = threadIdx.x;
    const int wid = tid >> 5;
    const size_t m0 = (size_t)blockIdx.x * 64;

    {
        const int row  = tid >> 1;
        const int half = (tid & 1) * 32;
        const float4* src = (const float4*)(g_hbuf + (m0 + row) * HID + half);
        __nv_bfloat16* ar = As + row * LDK + half;
#pragma unroll
        for (int i = 0; i < 8; i++) {
            float4 v = src[i];
            uint32_t h0, h1, h2, h3; float l0, l1, l2, l3;
            bsplit(v.x, h0, l0); bsplit(v.y, h1, l1);
            bsplit(v.z, h2, l2); bsplit(v.w, h3, l3);
            uint32_t hp0 = (h0 >> 16) | (h1 & 0xFFFF0000u);
            uint32_t hp1 = (h2 >> 16) | (h3 & 0xFFFF0000u);
            *(uint32_t*)(ar + 4 * i)           = hp0;
            *(uint32_t*)(ar + 4 * i + 2)       = hp1;
            *(uint32_t*)(ar + 64 + 4 * i)      = bfpack_rn(l0, l1);
            *(uint32_t*)(ar + 64 + 4 * i + 2)  = bfpack_rn(l2, l3);
            *(uint32_t*)(ar + 128 + 4 * i)     = hp0;
            *(uint32_t*)(ar + 128 + 4 * i + 2) = hp1;
        }
    }
    __syncthreads();

    const int mw = wid & 1;
    const int nw = wid >> 1;
    const __nv_bfloat16* a0p = As + (mw * 32) * LDK;
    const __nv_bfloat16* a1p = As + (mw * 32 + 16) * LDK;

#pragma unroll
    for (int nt = 0; nt < 8; nt++) {
        const int n0 = nw * 128 + nt * 16;
        wmma::fragment<wmma::accumulator, 16, 16, 16, float> c0, c1;
        wmma::fill_fragment(c0, 0.0f);
        wmma::fill_fragment(c1, 0.0f);
#pragma unroll
        for (int k = 0; k < 12; k++) {
            wmma::fragment<wmma::matrix_a, 16, 16, 16, __nv_bfloat16, wmma::row_major> a0, a1;
            wmma::fragment<wmma::matrix_b, 16, 16, 16, __nv_bfloat16, wmma::col_major> b;
            wmma::load_matrix_sync(a0, a0p + k * 16, LDK);
            wmma::load_matrix_sync(a1, a1p + k * 16, LDK);
            wmma::load_matrix_sync(b, g_wsp + n0 * LDB + k * 16, LDB);
            wmma::mma_sync(c0, a0, b, c0);
            wmma::mma_sync(c1, a1, b, c1);
        }
        float* o = g_xp + (m0 + (size_t)(mw * 32)) * NG + n0;
        wmma::store_matrix_sync(o, c0, NG, wmma::mem_row_major);
        wmma::store_matrix_sync(o + (size_t)16 * NG, c1, NG, wmma::mem_row_major);
    }
}

// ---------------------------------------------------------------------------
// Recurrent kernel v13: replicated h buffer + rotated weights + carried
// own-warp early partial (16 of 64 K computed pre-barrier each step).
// sh2[j] == sh2[j+64], so warp wp reads K in logical order starting at 16*wp
// with contiguous wrap-free addresses; weight regs loaded in matching rotated
// order (all register indices compile-time constant -> no spill).
// ---------------------------------------------------------------------------
template<int MODE>
__global__ __launch_bounds__(256, 1)
void lstm_rec(const float* __restrict__ x_in,
              const float* __restrict__ W_hh,
              const float* __restrict__ W_ih,
              const float* __restrict__ b_ih,
              const float* __restrict__ b_hh)
{
    __shared__ __align__(16) float sh2[2][2][2 * HID];   // replicated h
    __shared__ float sx[2][2][2];

    const int tid  = threadIdx.x;
    const int be   = tid >> 7;
    const int r    = tid & 127;
    const int j    = r >> 1;
    const int role = r & 1;
    const int wp   = (r >> 5);                // warp index within group, 0..3
    const int bg   = blockIdx.x * 2 + be;
    const int bid  = be + 1;

    const int rowA = role ? (64 + j) : j;     // (i|f)
    const int rowB = rowA + 128;              // (g|o)

    // Rotated weight load: logical quad i covers physical K-quad (4*wp+i)&15.
    u64 wA[32], wB[32];
    {
        const float* pa = W_hh + rowA * HID;
        const float* pb = W_hh + rowB * HID;
#pragma unroll
        for (int i = 0; i < 16; i++) {
            int q4 = ((4 * wp + i) & 15) * 4;          // physical K base
            float4 va = *(const float4*)(pa + q4);
            float4 vb = *(const float4*)(pb + q4);
            wA[2 * i] = pack2(va.x, va.y); wA[2 * i + 1] = pack2(va.z, va.w);
            wB[2 * i] = pack2(vb.x, vb.y); wB[2 * i + 1] = pack2(vb.z, vb.w);
        }
    }

    const float biasA = b_ih[rowA] + b_hh[rowA];
    const float biasB = b_ih[rowB] + b_hh[rowB];
    float wxA0 = 0.f, wxA1 = 0.f, wxB0 = 0.f, wxB1 = 0.f;
    if (MODE == 0) {
        wxA0 = W_ih[rowA * 2]; wxA1 = W_ih[rowA * 2 + 1];
        wxB0 = W_ih[rowB * 2]; wxB1 = W_ih[rowB * 2 + 1];
    }

    if (role) { sh2[0][be][j] = 0.f; sh2[0][be][j + HID] = 0.f; }

    float xn0 = 0.f, xn1 = 0.f;
    if (MODE == 0 && r == 0) {
        const float2* xq = (const float2*)(x_in + (size_t)bg * T_STEPS * 2);
        float2 x0 = xq[0]; sx[0][be][0] = x0.x; sx[0][be][1] = x0.y;
        float2 x1 = xq[1]; xn0 = x1.x; xn1 = x1.y;
    }

    const float* xpb = g_xp + (size_t)bg * T_STEPS * NG;
    float xpA0 = 0.f, xpB0 = 0.f, xpA1 = 0.f, xpB1 = 0.f;
    if (MODE >= 1) {
        xpA0 = xpb[rowA];      xpB0 = xpb[rowB];
        xpA1 = xpb[NG + rowA]; xpB1 = xpb[NG + rowB];
    }

    float c = 0.f;
    float* hb = g_hbuf + (size_t)bg * T_STEPS * HID + j;

    // accumulators carried across iterations (early partial seeds them);
    // h_{-1} = 0 -> zero seed is correct for t = 0.
    u64 aA0 = 0, aA1 = 0, aB0 = 0, aB1 = 0;
    __syncthreads();

    for (int t = 0; t < T_STEPS; t++) {
        const int p = t & 1;
        // ---- main matmul: quads i = 4..15 (other warps' h) ----
        const ulonglong2* HQ = (const ulonglong2*)&sh2[p][be][0];
#pragma unroll
        for (int i = 4; i < 16; i++) {
            ulonglong2 pv = HQ[wp * 4 + i];            // replicated, wrap-free
            ffma2(aA0, pv.x, wA[2 * i]); ffma2(aA1, pv.y, wA[2 * i + 1]);
            ffma2(aB0, pv.x, wB[2 * i]); ffma2(aB1, pv.y, wB[2 * i + 1]);
        }
        float zA, zB;
        {
            float u0, u1, u2, u3;
            unpack2(aA0, u0, u1); unpack2(aA1, u2, u3); zA = (u0 + u1) + (u2 + u3);
            unpack2(aB0, u0, u1); unpack2(aB1, u2, u3); zB = (u0 + u1) + (u2 + u3);
        }
        if (MODE == 0) {
            float xv0 = sx[p][be][0], xv1 = sx[p][be][1];
            zA += biasA + wxA0 * xv0 + wxA1 * xv1;
            zB += biasB + wxB0 * xv0 + wxB1 * xv1;
        } else {
            zA += xpA0 + biasA; zB += xpB0 + biasB;
        }

        if (MODE >= 1) {                               // distance-2 prefetch
            xpA0 = xpA1; xpB0 = xpB1;
            int tn = (t + 2 < T_STEPS) ? (t + 2) : (T_STEPS - 1);
            xpA1 = xpb[(size_t)tn * NG + rowA];
            xpB1 = xpb[(size_t)tn * NG + rowB];
        }

        // ---- pointwise ----
        float sA    = sigt(zA);                        // sig(i) | sig(f)
        float other = role ? sigt(zB) : tanha(zB);     // sig(o) | tanh(g)
        float send  = sA * other;                      // i*tanh(g) | --
        float ar    = __shfl_xor_sync(0xffffffffu, send, 1);
        if (role) {
            c = sA * c + ar;
            float h = other * tanha(c);
            sh2[p ^ 1][be][j] = h;
            sh2[p ^ 1][be][j + HID] = h;               // replica
            if (MODE <= 1) hb[(size_t)t * HID] = h;
            if (MODE == 2 && t == T_STEPS - 1) g_hfin[bg * HID + j] = h;
        }
        if (MODE == 0 && r == 0) {
            sx[p ^ 1][be][0] = xn0; sx[p ^ 1][be][1] = xn1;
            int tn = (t + 2 < T_STEPS) ? (t + 2) : (T_STEPS - 1);
            const float2* xq = (const float2*)(x_in + (size_t)bg * T_STEPS * 2);
            float2 xv = xq[tn]; xn0 = xv.x; xn1 = xv.y;
        }
        __syncwarp();

        // ---- early partial for t+1: own-warp K (quads 0..3), pre-barrier ----
        aA0 = 0; aA1 = 0; aB0 = 0; aB1 = 0;
        const ulonglong2* HQn = (const ulonglong2*)&sh2[p ^ 1][be][0];
#pragma unroll
        for (int i = 0; i < 4; i++) {
            ulonglong2 pv = HQn[wp * 4 + i];
            ffma2(aA0, pv.x, wA[2 * i]); ffma2(aA1, pv.y, wA[2 * i + 1]);
            ffma2(aB0, pv.x, wB[2 * i]); ffma2(aB1, pv.y, wB[2 * i + 1]);
        }
        gbar(bid);
    }
}

__global__ void final_linear_kernel(const float* __restrict__ W_out,
                                    const float* __restrict__ b_out,
                                    float* __restrict__ out)
{
    int idx = blockIdx.x * blockDim.x + threadIdx.x;
    if (idx >= BATCH * NOUT) return;
    int b = idx / NOUT, o = idx - b * NOUT;
    float s = b_out[o];
    const float* h  = &g_hfin[b * HID];
    const float* wr = &W_out[o * HID];
#pragma unroll 16
    for (int k = 0; k < HID; k++) s += h[k] * wr[k];
    out[idx] = s;
}

extern "C" void kernel_launch(void* const* d_in, const int* in_sizes, int n_in,
                              void* d_out, int out_size)
{
    const float* x    = (const float*)d_in[0];
    const float* Wih0 = (const float*)d_in[1];
    const float* Whh0 = (const float*)d_in[2];
    const float* bih0 = (const float*)d_in[3];
    const float* bhh0 = (const float*)d_in[4];
    const float* Wih1 = (const float*)d_in[5];
    const float* Whh1 = (const float*)d_in[6];
    const float* bih1 = (const float*)d_in[7];
    const float* bhh1 = (const float*)d_in[8];
    const float* Wih2 = (const float*)d_in[9];
    const float* Whh2 = (const float*)d_in[10];
    const float* bih2 = (const float*)d_in[11];
    const float* bhh2 = (const float*)d_in[12];
    const float* Wout = (const float*)d_in[13];
    const float* bout = (const float*)d_in[14];

    dim3 rgrid(BATCH / 2), rblock(256);
    dim3 ggrid(BATCH * T_STEPS / 64), gblock(128);

    lstm_rec<0><<<rgrid, rblock>>>(x, Whh0, Wih0, bih0, bhh0);
    wsplit<<<1, 256>>>(Wih1);
    xproj_wmma<<<ggrid, gblock>>>(0);
    lstm_rec<1><<<rgrid, rblock>>>(nullptr, Whh1, nullptr, bih1, bhh1);
    wsplit<<<1, 256>>>(Wih2);
    xproj_wmma<<<ggrid, gblock>>>(0);
    lstm_rec<2><<<rgrid, rblock>>>(nullptr, Whh2, nullptr, bih2, bhh2);
    final_linear_kernel<<<(BATCH * NOUT + 255) / 256, 256>>>(Wout, bout, (float*)d_out);
}

// round 14
// speedup vs baseline: 1.2063x; 1.2063x over previous
#include <cuda_runtime.h>
#include <cuda_bf16.h>
#include <mma.h>
#include <cstdint>

using namespace nvcuda;

#define T_STEPS 2048
#define BATCH   256
#define HID     64
#define NG      256
#define NOUT    11
#define LDK     200
#define LDB     208

typedef unsigned long long u64;

__device__ float g_hbuf[(size_t)BATCH * T_STEPS * HID];   // 128 MB
__device__ float g_xp[(size_t)BATCH * T_STEPS * NG];      // 512 MB
__device__ float g_hfin[BATCH * HID];
__device__ __align__(256) __nv_bfloat16 g_wsp[NG * LDB];  // split W_ih

// ---------------- scalar helpers ----------------
__device__ __forceinline__ u64 pack2(float a, float b) {
    u64 r; asm("mov.b64 %0, {%1,%2};" : "=l"(r) : "f"(a), "f"(b)); return r;
}
__device__ __forceinline__ void unpack2(u64 v, float& a, float& b) {
    asm("mov.b64 {%0,%1}, %2;" : "=f"(a), "=f"(b) : "l"(v));
}
__device__ __forceinline__ void ffma2(u64& d, u64 a, u64 b) {
    asm("fma.rn.f32x2 %0, %1, %2, %0;" : "+l"(d) : "l"(a), "l"(b));
}
__device__ __forceinline__ void fadd2(u64& d, u64 a) {
    asm("add.rn.f32x2 %0, %0, %1;" : "+l"(d) : "l"(a));
}
__device__ __forceinline__ float tanha(float x) {
    float y; asm("tanh.approx.f32 %0, %1;" : "=f"(y) : "f"(x)); return y;
}
__device__ __forceinline__ float sigt(float x) {
    return fmaf(0.5f, tanha(0.5f * x), 0.5f);
}
__device__ __forceinline__ void gbar(int id) {
    asm volatile("bar.sync %0, 128;" :: "r"(id) : "memory");
}
__device__ __forceinline__ void bsplit(float x, uint32_t& hibits, float& lo) {
    uint32_t u = __float_as_uint(x) & 0xFFFF0000u;
    hibits = u;
    lo = x - __uint_as_float(u);
}
__device__ __forceinline__ uint32_t bfpack_rn(float x0, float x1) {
    __nv_bfloat162 h = __floats2bfloat162_rn(x0, x1);
    return *(uint32_t*)&h;
}

// ---------------------------------------------------------------------------
// One-time W_ih split (R12, measured).
// ---------------------------------------------------------------------------
__global__ void wsplit(const float* __restrict__ W_ih)
{
    const int n = threadIdx.x;
    const float4* src = (const float4*)(W_ih + n * HID);
    __nv_bfloat16* br = g_wsp + n * LDB;
#pragma unroll
    for (int i = 0; i < 8; i++) {
        float4 v = src[i * 2];
        float4 w = src[i * 2 + 1];
        uint32_t h0, h1, h2, h3, h4, h5, h6, h7;
        float l0, l1, l2, l3, l4, l5, l6, l7;
        bsplit(v.x, h0, l0); bsplit(v.y, h1, l1);
        bsplit(v.z, h2, l2); bsplit(v.w, h3, l3);
        bsplit(w.x, h4, l4); bsplit(w.y, h5, l5);
        bsplit(w.z, h6, l6); bsplit(w.w, h7, l7);
        uint32_t hp0 = (h0 >> 16) | (h1 & 0xFFFF0000u);
        uint32_t hp1 = (h2 >> 16) | (h3 & 0xFFFF0000u);
        uint32_t hp2 = (h4 >> 16) | (h5 & 0xFFFF0000u);
        uint32_t hp3 = (h6 >> 16) | (h7 & 0xFFFF0000u);
        *(uint32_t*)(br + 8 * i)           = hp0;
        *(uint32_t*)(br + 8 * i + 2)       = hp1;
        *(uint32_t*)(br + 8 * i + 4)       = hp2;
        *(uint32_t*)(br + 8 * i + 6)       = hp3;
        *(uint32_t*)(br + 64 + 8 * i)      = hp0;
        *(uint32_t*)(br + 64 + 8 * i + 2)  = hp1;
        *(uint32_t*)(br + 64 + 8 * i + 4)  = hp2;
        *(uint32_t*)(br + 64 + 8 * i + 6)  = hp3;
        *(uint32_t*)(br + 128 + 8 * i)     = bfpack_rn(l0, l1);
        *(uint32_t*)(br + 128 + 8 * i + 2) = bfpack_rn(l2, l3);
        *(uint32_t*)(br + 128 + 8 * i + 4) = bfpack_rn(l4, l5);
        *(uint32_t*)(br + 128 + 8 * i + 6) = bfpack_rn(l6, l7);
    }
}

// ---------------------------------------------------------------------------
// WMMA x-projection (R12, measured ~330us/layer). Unchanged.
// ---------------------------------------------------------------------------
__global__ __launch_bounds__(128, 4)
void xproj_wmma(int dummy)
{
    __shared__ __align__(16) __nv_bfloat16 As[64 * LDK];

    const int tid = threadIdx.x;
    const int wid = tid >> 5;
    const size_t m0 = (size_t)blockIdx.x * 64;

    {
        const int row  = tid >> 1;
        const int half = (tid & 1) * 32;
        const float4* src = (const float4*)(g_hbuf + (m0 + row) * HID + half);
        __nv_bfloat16* ar = As + row * LDK + half;
#pragma unroll
        for (int i = 0; i < 8; i++) {
            float4 v = src[i];
            uint32_t h0, h1, h2, h3; float l0, l1, l2, l3;
            bsplit(v.x, h0, l0); bsplit(v.y, h1, l1);
            bsplit(v.z, h2, l2); bsplit(v.w, h3, l3);
            uint32_t hp0 = (h0 >> 16) | (h1 & 0xFFFF0000u);
            uint32_t hp1 = (h2 >> 16) | (h3 & 0xFFFF0000u);
            *(uint32_t*)(ar + 4 * i)           = hp0;
            *(uint32_t*)(ar + 4 * i + 2)       = hp1;
            *(uint32_t*)(ar + 64 + 4 * i)      = bfpack_rn(l0, l1);
            *(uint32_t*)(ar + 64 + 4 * i + 2)  = bfpack_rn(l2, l3);
            *(uint32_t*)(ar + 128 + 4 * i)     = hp0;
            *(uint32_t*)(ar + 128 + 4 * i + 2) = hp1;
        }
    }
    __syncthreads();

    const int mw = wid & 1;
    const int nw = wid >> 1;
    const __nv_bfloat16* a0p = As + (mw * 32) * LDK;
    const __nv_bfloat16* a1p = As + (mw * 32 + 16) * LDK;

#pragma unroll
    for (int nt = 0; nt < 8; nt++) {
        const int n0 = nw * 128 + nt * 16;
        wmma::fragment<wmma::accumulator, 16, 16, 16, float> c0, c1;
        wmma::fill_fragment(c0, 0.0f);
        wmma::fill_fragment(c1, 0.0f);
#pragma unroll
        for (int k = 0; k < 12; k++) {
            wmma::fragment<wmma::matrix_a, 16, 16, 16, __nv_bfloat16, wmma::row_major> a0, a1;
            wmma::fragment<wmma::matrix_b, 16, 16, 16, __nv_bfloat16, wmma::col_major> b;
            wmma::load_matrix_sync(a0, a0p + k * 16, LDK);
            wmma::load_matrix_sync(a1, a1p + k * 16, LDK);
            wmma::load_matrix_sync(b, g_wsp + n0 * LDB + k * 16, LDB);
            wmma::mma_sync(c0, a0, b, c0);
            wmma::mma_sync(c1, a1, b, c1);
        }
        float* o = g_xp + (m0 + (size_t)(mw * 32)) * NG + n0;
        wmma::store_matrix_sync(o, c0, NG, wmma::mem_row_major);
        wmma::store_matrix_sync(o + (size_t)16 * NG, c1, NG, wmma::mem_row_major);
    }
}

// ---------------------------------------------------------------------------
// Recurrent kernel: R12 loop (best measured) + packed fadd2 reduce.
// ---------------------------------------------------------------------------
template<int MODE>
__global__ __launch_bounds__(256, 1)
void lstm_rec(const float* __restrict__ x_in,
              const float* __restrict__ W_hh,
              const float* __restrict__ W_ih,
              const float* __restrict__ b_ih,
              const float* __restrict__ b_hh)
{
    __shared__ __align__(16) float sh[2][2][HID];
    __shared__ float sx[2][2][2];

    const int tid  = threadIdx.x;
    const int be   = tid >> 7;
    const int r    = tid & 127;
    const int j    = r >> 1;
    const int role = r & 1;
    const int bg   = blockIdx.x * 2 + be;
    const int bid  = be + 1;

    const int rowA = role ? (64 + j) : j;         // (i|f)
    const int rowB = rowA + 128;                  // (g|o)

    u64 wA[32], wB[32];
    {
        const float4* pa = (const float4*)(W_hh + rowA * HID);
        const float4* pb = (const float4*)(W_hh + rowB * HID);
#pragma unroll
        for (int i = 0; i < 16; i++) {
            float4 va = pa[i], vb = pb[i];
            wA[2 * i] = pack2(va.x, va.y); wA[2 * i + 1] = pack2(va.z, va.w);
            wB[2 * i] = pack2(vb.x, vb.y); wB[2 * i + 1] = pack2(vb.z, vb.w);
        }
    }

    const float biasA = b_ih[rowA] + b_hh[rowA];
    const float biasB = b_ih[rowB] + b_hh[rowB];
    float wxA0 = 0.f, wxA1 = 0.f, wxB0 = 0.f, wxB1 = 0.f;
    if (MODE == 0) {
        wxA0 = W_ih[rowA * 2]; wxA1 = W_ih[rowA * 2 + 1];
        wxB0 = W_ih[rowB * 2]; wxB1 = W_ih[rowB * 2 + 1];
    }

    if (role) sh[0][be][j] = 0.f;

    float xn0 = 0.f, xn1 = 0.f;
    if (MODE == 0 && r == 0) {
        const float2* xq = (const float2*)(x_in + (size_t)bg * T_STEPS * 2);
        float2 x0 = xq[0]; sx[0][be][0] = x0.x; sx[0][be][1] = x0.y;
        float2 x1 = xq[1]; xn0 = x1.x; xn1 = x1.y;
    }

    const float* xpb = g_xp + (size_t)bg * T_STEPS * NG;
    float xpA0 = 0.f, xpB0 = 0.f, xpA1 = 0.f, xpB1 = 0.f;
    if (MODE >= 1) {
        xpA0 = xpb[rowA];      xpB0 = xpb[rowB];
        xpA1 = xpb[NG + rowA]; xpB1 = xpb[NG + rowB];
    }

    float c = 0.f;
    float* hb = g_hbuf + (size_t)bg * T_STEPS * HID + j;
    __syncthreads();

    for (int t = 0; t < T_STEPS; t++) {
        const int p = t & 1;
        const ulonglong2* hr = (const ulonglong2*)sh[p][be];
        u64 aA0 = 0, aA1 = 0, aB0 = 0, aB1 = 0;
#pragma unroll
        for (int k = 0; k < 16; k++) {
            ulonglong2 pv = hr[k];                 // broadcast LDS.128
            ffma2(aA0, pv.x, wA[2 * k]); ffma2(aA1, pv.y, wA[2 * k + 1]);
            ffma2(aB0, pv.x, wB[2 * k]); ffma2(aB1, pv.y, wB[2 * k + 1]);
        }
        // packed reduce: shorter chain than scalar unpack tree
        fadd2(aA0, aA1); fadd2(aB0, aB1);
        float zA, zB;
        {
            float u0, u1;
            unpack2(aA0, u0, u1); zA = u0 + u1;
            unpack2(aB0, u0, u1); zB = u0 + u1;
        }
        if (MODE == 0) {
            float xv0 = sx[p][be][0], xv1 = sx[p][be][1];
            zA += biasA + wxA0 * xv0 + wxA1 * xv1;
            zB += biasB + wxB0 * xv0 + wxB1 * xv1;
        } else {
            zA += xpA0 + biasA; zB += xpB0 + biasB;
        }

        if (MODE >= 1) {
            xpA0 = xpA1; xpB0 = xpB1;
            int tn = (t + 2 < T_STEPS) ? (t + 2) : (T_STEPS - 1);
            xpA1 = xpb[(size_t)tn * NG + rowA];
            xpB1 = xpb[(size_t)tn * NG + rowB];
        }

        float sA    = sigt(zA);                        // sig(i) | sig(f)
        float other = role ? sigt(zB) : tanha(zB);     // sig(o) | tanh(g)
        float send  = sA * other;                      // i*tanh(g) | --
        float ar    = __shfl_xor_sync(0xffffffffu, send, 1);
        if (role) {
            c = sA * c + ar;
            float h = other * tanha(c);
            sh[p ^ 1][be][j] = h;                      // critical (next step)
            if (MODE <= 1) hb[(size_t)t * HID] = h;    // fire-and-forget
            if (MODE == 2 && t == T_STEPS - 1) g_hfin[bg * HID + j] = h;
        }
        if (MODE == 0 && r == 0) {
            sx[p ^ 1][be][0] = xn0; sx[p ^ 1][be][1] = xn1;
            int tn = (t + 2 < T_STEPS) ? (t + 2) : (T_STEPS - 1);
            const float2* xq = (const float2*)(x_in + (size_t)bg * T_STEPS * 2);
            float2 xv = xq[tn]; xn0 = xv.x; xn1 = xv.y;
        }
        gbar(bid);
    }
}

__global__ void final_linear_kernel(const float* __restrict__ W_out,
                                    const float* __restrict__ b_out,
                                    float* __restrict__ out)
{
    int idx = blockIdx.x * blockDim.x + threadIdx.x;
    if (idx >= BATCH * NOUT) return;
    int b = idx / NOUT, o = idx - b * NOUT;
    float s = b_out[o];
    const float* h  = &g_hfin[b * HID];
    const float* wr = &W_out[o * HID];
#pragma unroll 16
    for (int k = 0; k < HID; k++) s += h[k] * wr[k];
    out[idx] = s;
}

extern "C" void kernel_launch(void* const* d_in, const int* in_sizes, int n_in,
                              void* d_out, int out_size)
{
    const float* x    = (const float*)d_in[0];
    const float* Wih0 = (const float*)d_in[1];
    const float* Whh0 = (const float*)d_in[2];
    const float* bih0 = (const float*)d_in[3];
    const float* bhh0 = (const float*)d_in[4];
    const float* Wih1 = (const float*)d_in[5];
    const float* Whh1 = (const float*)d_in[6];
    const float* bih1 = (const float*)d_in[7];
    const float* bhh1 = (const float*)d_in[8];
    const float* Wih2 = (const float*)d_in[9];
    const float* Whh2 = (const float*)d_in[10];
    const float* bih2 = (const float*)d_in[11];
    const float* bhh2 = (const float*)d_in[12];
    const float* Wout = (const float*)d_in[13];
    const float* bout = (const float*)d_in[14];

    dim3 rgrid(BATCH / 2), rblock(256);
    dim3 ggrid(BATCH * T_STEPS / 64), gblock(128);

    lstm_rec<0><<<rgrid, rblock>>>(x, Whh0, Wih0, bih0, bhh0);
    wsplit<<<1, 256>>>(Wih1);
    xproj_wmma<<<ggrid, gblock>>>(0);
    lstm_rec<1><<<rgrid, rblock>>>(nullptr, Whh1, nullptr, bih1, bhh1);
    wsplit<<<1, 256>>>(Wih2);
    xproj_wmma<<<ggrid, gblock>>>(0);
    lstm_rec<2><<<rgrid, rblock>>>(nullptr, Whh2, nullptr, bih2, bhh2);
    final_linear_kernel<<<(BATCH * NOUT + 255) / 256, 256>>>(Wout, bout, (float*)d_out);
}